// round 14
// baseline (speedup 1.0000x reference)
#include <cuda_runtime.h>
#include <math_constants.h>
#include <math.h>

#define NUM_VIEW 300
#define NPAIR    150   // view pairs
#define WVIEW    80    // window: views scanned per point (covering-radius bound)
#define WP       20    // window pairs per lane
#define W0MAX    (NUM_VIEW - WVIEW)   // 220
#define TPB      448   // threads per block (2 lanes/point)

// Codebook passed BY VALUE as a kernel parameter (2.4KB, constant bank).
// Pair j (views 2j, 2j+1):  A[j] = bits of {x0, x1, y0, y1}
// z is analytic (z_i = (2i+1)/300 - 1) and the -|v|^2/2 term is an
// argmax-invariant constant (up to ~1e-7), so only x,y are stored.
struct NPCodebook {
    ulonglong2 A[NPAIR];
};

__device__ __forceinline__ unsigned long long np_fma2(
        unsigned long long a, unsigned long long b, unsigned long long c) {
    unsigned long long d;
    asm("fma.rn.f32x2 %0, %1, %2, %3;" : "=l"(d) : "l"(a), "l"(b), "l"(c));
    return d;
}

__device__ __forceinline__ unsigned long long np_add2(
        unsigned long long a, unsigned long long b) {
    unsigned long long d;
    asm("add.rn.f32x2 %0, %1, %2;" : "=l"(d) : "l"(a), "l"(b));
    return d;
}

__device__ __forceinline__ unsigned long long np_pack2(float lo, float hi) {
    unsigned long long d;
    asm("mov.b64 %0, {%1, %2};" : "=l"(d) : "f"(lo), "f"(hi));
    return d;
}

__device__ __forceinline__ void np_unpack2(float& lo, float& hi,
                                           unsigned long long v) {
    asm("mov.b64 {%0, %1}, %2;" : "=f"(lo), "=f"(hi) : "l"(v));
}

__device__ __forceinline__ void np_merge_max(float& s0, int& i0, float s1, int i1) {
    // first-max (lowest index) wins on ties — matches argmin-first semantics
    bool g = (s1 > s0) || (s1 == s0 && i1 < i0);
    s0 = g ? s1 : s0;
    i0 = g ? i1 : i0;
}

// 2 threads per point. Views sorted by z -> winner lies within +-40 indices
// of i_c = round((u_z+1)*150). Codebook xy: kernel param -> smem (2.4KB).
// All 20 window LDS.128 hoisted into a register array BEFORE consumption so
// the loads pipeline back-to-back instead of serializing against the FMA chain.
// MODE 0: indices written as float32 (output = 13*P floats)
// MODE 1: indices written as int64 bit-pattern (output = 14*P float slots)
template <int MODE>
__global__ void __launch_bounds__(TPB, 1)
np_main_kernel(const __grid_constant__ NPCodebook cb,
               const float* __restrict__ normals,
               const int*   __restrict__ idxs,
               float*       __restrict__ out,
               int N, int S, int logS, int P) {
    __shared__ ulonglong2 sA[NPAIR];

    int tid = threadIdx.x;
    int t   = blockIdx.x * TPB + tid;
    int p   = t >> 1;
    int h   = t & 1;
    int pc  = (p < P) ? p : (P - 1);  // clamp, keep barrier convergent

    // gather loads issued first — overlap with codebook preload
    int b   = (logS >= 0) ? (pc >> logS) : (pc / S);
    int idx = idxs[pc];
    const float* nptr = normals + ((long long)b * N + idx) * 3;
    float nx = __ldg(nptr + 0);
    float ny = __ldg(nptr + 1);
    float nz = __ldg(nptr + 2);

    // codebook param (constant bank) -> shared
    for (int i = tid; i < NPAIR; i += TPB)
        sA[i] = cb.A[i];
    __syncthreads();

    // window center from normalized z (approximation fine: 1.4x margin)
    float nn  = fmaf(nx, nx, fmaf(ny, ny, nz * nz));
    float rs  = rsqrtf(nn);            // reused below for ax normalization
    float uz  = nz * rs;
    int   ic  = __float2int_rn(fmaf(uz, 150.0f, 150.0f));
    int   w0  = ic - (WVIEW / 2);
    w0 = (w0 < 0) ? 0 : ((w0 > W0MAX) ? W0MAX : w0);
    w0 &= ~1;                 // even start so pairs align
    int jp = w0 >> 1;         // first window pair

    // ---- load phase: all 20 window pairs -> registers, back-to-back LDS ----
    // V[m]   = pair (jp + 2m + h)        m = 0..9   (segment A)
    // V[m+10]= pair (jp + 2m + h + 20)   m = 0..9   (segment B)
    ulonglong2 V[WP];
#pragma unroll
    for (int m = 0; m < 10; m++) {
        int jA = jp + 2 * m + h;
        V[m]      = sA[jA];
        V[m + 10] = sA[jA + 20];
    }

    unsigned long long pnx = np_pack2(nx, nx);
    unsigned long long pny = np_pack2(ny, ny);

    // analytic z-terms: pair j holds views 2j (lo), 2j+1 (hi);
    // z_lo(j) = (4j+1)/300 - 1, z_hi = z_lo + 2/300.
    const float inv300 = 1.0f / 300.0f;
    int jA0 = jp + h;
    float zAlo = fmaf((float)(4 * jA0 + 1), inv300, -1.0f);
    float zAhi = zAlo + 2.0f * inv300;
    unsigned long long pzA = np_pack2(nz * zAlo, nz * zAhi);
    float zstep = nz * (80.0f * inv300);
    unsigned long long pzB = np_add2(pzA, np_pack2(zstep, zstep));
    float dzf = nz * (8.0f * inv300);
    unsigned long long dpz = np_pack2(dzf, dzf);

    // ---- compute phase: register-resident, 2 pairs/iter ----
    float bAl = -CUDART_INF_F, bAh = -CUDART_INF_F,
          bBl = -CUDART_INF_F, bBh = -CUDART_INF_F;
    int   mAl = 0, mAh = 0, mBl = 0, mBh = 0;

#pragma unroll
    for (int m = 0; m < 10; m++) {
        unsigned long long s0 = np_fma2(pnx, V[m].x,
                                        np_fma2(pny, V[m].y, pzA));
        unsigned long long s1 = np_fma2(pnx, V[m + 10].x,
                                        np_fma2(pny, V[m + 10].y, pzB));
        pzA = np_add2(pzA, dpz);
        pzB = np_add2(pzB, dpz);

        float f0l, f0h, f1l, f1h;
        np_unpack2(f0l, f0h, s0);
        np_unpack2(f1l, f1h, s1);

        // strict > keeps first-win; ternary form -> SEL (4-cyc) chains
        bool gAl = f0l > bAl;  bAl = gAl ? f0l : bAl;  mAl = gAl ? m : mAl;
        bool gAh = f0h > bAh;  bAh = gAh ? f0h : bAh;  mAh = gAh ? m : mAh;
        bool gBl = f1l > bBl;  bBl = gBl ? f1l : bBl;  mBl = gBl ? m : mBl;
        bool gBh = f1h > bBh;  bBh = gBh ? f1h : bBh;  mBh = gBh ? m : mBh;
    }

    // reconstruct global view indices
    int iAl = 2 * (jp + 2 * mAl + h);
    int iAh = 2 * (jp + 2 * mAh + h) + 1;
    int iBl = 2 * (jp + 2 * mBl + h + 20);
    int iBh = 2 * (jp + 2 * mBh + h + 20) + 1;

    // merge 4 accumulators (index tie-break keeps exact first-win semantics)
    np_merge_max(bAl, iAl, bAh, iAh);
    np_merge_max(bBl, iBl, bBh, iBh);
    np_merge_max(bAl, iAl, bBl, iBl);

    // merge across the lane pair
    float os = __shfl_xor_sync(0xffffffffu, bAl, 1);
    int   oi = __shfl_xor_sync(0xffffffffu, iAl, 1);
    np_merge_max(bAl, iAl, os, oi);
    int bi = iAl;

    // --- rotation matrix from towards = -n, angle = 0 (R1 = I, rot = R2) ---
    // ax = -n normalized: reuse rs = rsqrtf(nn) (|-n| = |n|).
    float ax_x = -nx * rs, ax_y = -ny * rs, ax_z = -nz * rs;
    // ay = (ny, -nx, 0) or (0,1,0) if degenerate; normalize with MUFU.RSQ.
    float qy = fmaf(ny, ny, nx * nx);
    bool  deg = (qy == 0.0f);
    float ay_x = deg ? 0.0f : ny;
    float ay_y = deg ? 1.0f : -nx;
    float invy = rsqrtf(deg ? 1.0f : qy);
    ay_x *= invy;
    ay_y *= invy;
    const float ay_z = 0.0f;
    // az = cross(ax, ay)
    float az_x = ax_y * ay_z - ax_z * ay_y;
    float az_y = ax_z * ay_x - ax_x * ay_z;
    float az_z = ax_x * ay_y - ax_y * ay_x;

    // --- outputs (stores split between the two lanes of the pair) ---
    if (p < P) {
        float* out_xyz;
        float* out_rot;
        if (MODE == 0) {
            out_xyz = out + P;
            out_rot = out + P + 3 * (long long)P;
        } else {
            out_xyz = out + 2 * (long long)P;
            out_rot = out + 2 * (long long)P + 3 * (long long)P;
        }

        long long base3 = (long long)p * 3;
        long long base9 = (long long)p * 9;

        if (h == 0) {
            if (MODE == 0) {
                out[p] = (float)bi;
            } else {
                ((long long*)out)[p] = (long long)bi;
            }
            out_xyz[base3 + 0] = nx;
            out_xyz[base3 + 1] = ny;
            out_xyz[base3 + 2] = nz;
            // row-major [r][c]: col0 = ax, col1 = ay, col2 = az
            out_rot[base9 + 0] = ax_x;
            out_rot[base9 + 1] = ay_x;
            out_rot[base9 + 2] = az_x;
            out_rot[base9 + 3] = ax_y;
        } else {
            out_rot[base9 + 4] = ay_y;
            out_rot[base9 + 5] = az_y;
            out_rot[base9 + 6] = ax_z;
            out_rot[base9 + 7] = ay_z;
            out_rot[base9 + 8] = az_z;
        }
    }
}

// Host-side codebook build (fp64 libm matches numpy's float64 path).
static void np_build_codebook(NPCodebook* cb) {
    const double PHI = (sqrt(5.0) - 1.0) * 0.5;
    for (int i = 0; i < NUM_VIEW; i++) {
        double di = (double)i;
        double zi = (2.0 * di + 1.0) / (double)NUM_VIEW - 1.0;
        double r2 = 1.0 - zi * zi;
        if (r2 < 0.0) r2 = 0.0;
        double r  = sqrt(r2);
        double ang = 2.0 * di * M_PI * PHI;
        float xf = (float)(r * cos(ang));
        float yf = (float)(r * sin(ang));

        int j = i >> 1;
        int o = i & 1;
        float* fa = (float*)&cb->A[j];
        fa[0 + o] = xf;
        fa[2 + o] = yf;
    }
}

extern "C" void kernel_launch(void* const* d_in, const int* in_sizes, int n_in,
                              void* d_out, int out_size) {
    const float* normals = (const float*)d_in[0];
    const int*   idxs    = (const int*)d_in[1];
    float*       out     = (float*)d_out;

    const int B = 8;
    int P = in_sizes[1];            // B*S = 32768
    int S = P / B;                  // 4096
    int N = in_sizes[0] / (B * 3);  // 500000

    int logS = -1;
    if (S > 0 && (S & (S - 1)) == 0) {
        logS = 0;
        while ((1 << logS) < S) logS++;
    }

    NPCodebook cb;
    np_build_codebook(&cb);

    // 2 lanes per point; single kernel, one balanced wave: 147 x 448
    long long total = 2LL * P;
    int blocks = (int)((total + TPB - 1) / TPB);
    if (out_size == 14 * P) {
        np_main_kernel<1><<<blocks, TPB>>>(cb, normals, idxs, out, N, S, logS, P);
    } else {
        np_main_kernel<0><<<blocks, TPB>>>(cb, normals, idxs, out, N, S, logS, P);
    }
}

// round 15
// speedup vs baseline: 1.0037x; 1.0037x over previous
#include <cuda_runtime.h>
#include <math_constants.h>
#include <math.h>

#define NUM_VIEW 300
#define NPAIR    150   // view pairs
#define WVIEW    64    // window: views scanned per point (bound ±23, margin 1.39x)
#define WP       32    // window pairs per thread
#define W0MAX    (NUM_VIEW - WVIEW)   // 236
#define TPB      224   // threads per block (1 lane/point; 147 blocks = 1 wave)

// Codebook passed BY VALUE as a kernel parameter (2.4KB, constant bank).
// Pair j (views 2j, 2j+1):  A[j] = bits of {x0, x1, y0, y1}
// z is analytic (z_i = (2i+1)/300 - 1) and the -|v|^2/2 term is an
// argmax-invariant constant (up to ~1e-7), so only x,y are stored.
struct NPCodebook {
    ulonglong2 A[NPAIR];
};

__device__ __forceinline__ unsigned long long np_fma2(
        unsigned long long a, unsigned long long b, unsigned long long c) {
    unsigned long long d;
    asm("fma.rn.f32x2 %0, %1, %2, %3;" : "=l"(d) : "l"(a), "l"(b), "l"(c));
    return d;
}

__device__ __forceinline__ unsigned long long np_add2(
        unsigned long long a, unsigned long long b) {
    unsigned long long d;
    asm("add.rn.f32x2 %0, %1, %2;" : "=l"(d) : "l"(a), "l"(b));
    return d;
}

__device__ __forceinline__ unsigned long long np_pack2(float lo, float hi) {
    unsigned long long d;
    asm("mov.b64 %0, {%1, %2};" : "=l"(d) : "f"(lo), "f"(hi));
    return d;
}

__device__ __forceinline__ void np_unpack2(float& lo, float& hi,
                                           unsigned long long v) {
    asm("mov.b64 {%0, %1}, %2;" : "=f"(lo), "=f"(hi) : "l"(v));
}

__device__ __forceinline__ void np_merge_max(float& s0, int& i0, float s1, int i1) {
    // first-max (lowest index) wins on ties — matches argmin-first semantics
    bool g = (s1 > s0) || (s1 == s0 && i1 < i0);
    s0 = g ? s1 : s0;
    i0 = g ? i1 : i0;
}

// ONE thread per point. Views sorted by z -> winner lies within +-32 indices
// of i_c = round((u_z+1)*150). Thread scans pairs jp..jp+31:
//   segment A = pairs jp+m,      m = 0..15
//   segment B = pairs jp+16+m,   m = 0..15
// No cross-lane merge, no duplicated gather/epilogue work.
// MODE 0: indices written as float32 (output = 13*P floats)
// MODE 1: indices written as int64 bit-pattern (output = 14*P float slots)
template <int MODE>
__global__ void __launch_bounds__(TPB, 1)
np_main_kernel(const __grid_constant__ NPCodebook cb,
               const float* __restrict__ normals,
               const int*   __restrict__ idxs,
               float*       __restrict__ out,
               int N, int S, int logS, int P) {
    __shared__ ulonglong2 sA[NPAIR];

    int tid = threadIdx.x;
    int p   = blockIdx.x * TPB + tid;
    int pc  = (p < P) ? p : (P - 1);  // clamp, keep barrier convergent

    // gather loads issued first — overlap with codebook preload
    int b   = (logS >= 0) ? (pc >> logS) : (pc / S);
    int idx = idxs[pc];
    const float* nptr = normals + ((long long)b * N + idx) * 3;
    float nx = __ldg(nptr + 0);
    float ny = __ldg(nptr + 1);
    float nz = __ldg(nptr + 2);

    // codebook param (constant bank) -> shared
    for (int i = tid; i < NPAIR; i += TPB)
        sA[i] = cb.A[i];
    __syncthreads();

    // window center from normalized z
    float nn  = fmaf(nx, nx, fmaf(ny, ny, nz * nz));
    float rs  = rsqrtf(nn);            // reused below for ax normalization
    float uz  = nz * rs;
    int   ic  = __float2int_rn(fmaf(uz, 150.0f, 150.0f));
    int   w0  = ic - (WVIEW / 2);
    w0 = (w0 < 0) ? 0 : ((w0 > W0MAX) ? W0MAX : w0);
    w0 &= ~1;                 // even start so pairs align
    int jp = w0 >> 1;         // first window pair

    // ---- load phase: all 32 window pairs -> registers, back-to-back LDS ----
    ulonglong2 V[WP];
#pragma unroll
    for (int m = 0; m < 16; m++) {
        V[m]      = sA[jp + m];
        V[m + 16] = sA[jp + 16 + m];
    }

    unsigned long long pnx = np_pack2(nx, nx);
    unsigned long long pny = np_pack2(ny, ny);

    // analytic z-terms: pair j holds views 2j (lo), 2j+1 (hi);
    // z_lo(j) = (4j+1)/300 - 1, z_hi = z_lo + 2/300. Per pair step dz = 4/300.
    const float inv300 = 1.0f / 300.0f;
    float zAlo = fmaf((float)(4 * jp + 1), inv300, -1.0f);
    float zAhi = zAlo + 2.0f * inv300;
    unsigned long long pzA = np_pack2(nz * zAlo, nz * zAhi);
    float zstep = nz * (64.0f * inv300);   // +16 pairs
    unsigned long long pzB = np_add2(pzA, np_pack2(zstep, zstep));
    float dzf = nz * (4.0f * inv300);
    unsigned long long dpz = np_pack2(dzf, dzf);

    // ---- compute phase: register-resident, 2 pairs/iter, 16 iters ----
    float bAl = -CUDART_INF_F, bAh = -CUDART_INF_F,
          bBl = -CUDART_INF_F, bBh = -CUDART_INF_F;
    int   mAl = 0, mAh = 0, mBl = 0, mBh = 0;

#pragma unroll
    for (int m = 0; m < 16; m++) {
        unsigned long long s0 = np_fma2(pnx, V[m].x,
                                        np_fma2(pny, V[m].y, pzA));
        unsigned long long s1 = np_fma2(pnx, V[m + 16].x,
                                        np_fma2(pny, V[m + 16].y, pzB));
        pzA = np_add2(pzA, dpz);
        pzB = np_add2(pzB, dpz);

        float f0l, f0h, f1l, f1h;
        np_unpack2(f0l, f0h, s0);
        np_unpack2(f1l, f1h, s1);

        // strict > keeps first-win; ternary form -> SEL (4-cyc) chains
        bool gAl = f0l > bAl;  bAl = gAl ? f0l : bAl;  mAl = gAl ? m : mAl;
        bool gAh = f0h > bAh;  bAh = gAh ? f0h : bAh;  mAh = gAh ? m : mAh;
        bool gBl = f1l > bBl;  bBl = gBl ? f1l : bBl;  mBl = gBl ? m : mBl;
        bool gBh = f1h > bBh;  bBh = gBh ? f1h : bBh;  mBh = gBh ? m : mBh;
    }

    // reconstruct global view indices
    int iAl = 2 * (jp + mAl);
    int iAh = 2 * (jp + mAh) + 1;
    int iBl = 2 * (jp + 16 + mBl);
    int iBh = 2 * (jp + 16 + mBh) + 1;

    // merge 4 accumulators (index tie-break keeps exact first-win semantics)
    np_merge_max(bAl, iAl, bAh, iAh);
    np_merge_max(bBl, iBl, bBh, iBh);
    np_merge_max(bAl, iAl, bBl, iBl);
    int bi = iAl;

    // --- rotation matrix from towards = -n, angle = 0 (R1 = I, rot = R2) ---
    float ax_x = -nx * rs, ax_y = -ny * rs, ax_z = -nz * rs;
    float qy = fmaf(ny, ny, nx * nx);
    bool  deg = (qy == 0.0f);
    float ay_x = deg ? 0.0f : ny;
    float ay_y = deg ? 1.0f : -nx;
    float invy = rsqrtf(deg ? 1.0f : qy);
    ay_x *= invy;
    ay_y *= invy;
    const float ay_z = 0.0f;
    float az_x = ax_y * ay_z - ax_z * ay_y;
    float az_y = ax_z * ay_x - ax_x * ay_z;
    float az_z = ax_x * ay_y - ax_y * ay_x;

    // --- outputs (all 13 values from this thread) ---
    if (p < P) {
        float* out_xyz;
        float* out_rot;
        if (MODE == 0) {
            out[p] = (float)bi;
            out_xyz = out + P;
            out_rot = out + P + 3 * (long long)P;
        } else {
            ((long long*)out)[p] = (long long)bi;
            out_xyz = out + 2 * (long long)P;
            out_rot = out + 2 * (long long)P + 3 * (long long)P;
        }

        long long base3 = (long long)p * 3;
        long long base9 = (long long)p * 9;

        out_xyz[base3 + 0] = nx;
        out_xyz[base3 + 1] = ny;
        out_xyz[base3 + 2] = nz;
        // row-major [r][c]: col0 = ax, col1 = ay, col2 = az
        out_rot[base9 + 0] = ax_x;
        out_rot[base9 + 1] = ay_x;
        out_rot[base9 + 2] = az_x;
        out_rot[base9 + 3] = ax_y;
        out_rot[base9 + 4] = ay_y;
        out_rot[base9 + 5] = az_y;
        out_rot[base9 + 6] = ax_z;
        out_rot[base9 + 7] = ay_z;
        out_rot[base9 + 8] = az_z;
    }
}

// Host-side codebook build (fp64 libm matches numpy's float64 path).
static void np_build_codebook(NPCodebook* cb) {
    const double PHI = (sqrt(5.0) - 1.0) * 0.5;
    for (int i = 0; i < NUM_VIEW; i++) {
        double di = (double)i;
        double zi = (2.0 * di + 1.0) / (double)NUM_VIEW - 1.0;
        double r2 = 1.0 - zi * zi;
        if (r2 < 0.0) r2 = 0.0;
        double r  = sqrt(r2);
        double ang = 2.0 * di * M_PI * PHI;
        float xf = (float)(r * cos(ang));
        float yf = (float)(r * sin(ang));

        int j = i >> 1;
        int o = i & 1;
        float* fa = (float*)&cb->A[j];
        fa[0 + o] = xf;
        fa[2 + o] = yf;
    }
}

extern "C" void kernel_launch(void* const* d_in, const int* in_sizes, int n_in,
                              void* d_out, int out_size) {
    const float* normals = (const float*)d_in[0];
    const int*   idxs    = (const int*)d_in[1];
    float*       out     = (float*)d_out;

    const int B = 8;
    int P = in_sizes[1];            // B*S = 32768
    int S = P / B;                  // 4096
    int N = in_sizes[0] / (B * 3);  // 500000

    int logS = -1;
    if (S > 0 && (S & (S - 1)) == 0) {
        logS = 0;
        while ((1 << logS) < S) logS++;
    }

    NPCodebook cb;
    np_build_codebook(&cb);

    // 1 lane per point; single kernel, one balanced wave: 147 x 224
    int blocks = (P + TPB - 1) / TPB;
    if (out_size == 14 * P) {
        np_main_kernel<1><<<blocks, TPB>>>(cb, normals, idxs, out, N, S, logS, P);
    } else {
        np_main_kernel<0><<<blocks, TPB>>>(cb, normals, idxs, out, N, S, logS, P);
    }
}